// round 3
// baseline (speedup 1.0000x reference)
#include <cuda_runtime.h>
#include <cuda_bf16.h>

#define BATCH       32768
#define IN_CH       512
#define OUT_CH      1024
#define NP          17
#define NSTEPS      3

#define TOTAL4      (BATCH * IN_CH / 4)     // 4,194,304 threads
#define THREADS     256

__device__ __forceinline__ float f_tanh(float x){ float r; asm("tanh.approx.f32 %0,%1;" : "=f"(r) : "f"(x)); return r; }
__device__ __forceinline__ float f_sin (float x){ float r; asm("sin.approx.f32 %0,%1;"  : "=f"(r) : "f"(x)); return r; }
__device__ __forceinline__ float f_cos (float x){ float r; asm("cos.approx.f32 %0,%1;"  : "=f"(r) : "f"(x)); return r; }

#define MAGIC 12582912.0f   // 2^23 + 2^22: w + MAGIC has round(w) in low mantissa bits

__global__ void __launch_bounds__(THREADS)
macunit_kernel(const float4* __restrict__ data,
               const float*  __restrict__ angles,
               const float*  __restrict__ velocity,
               const float*  __restrict__ attention,
               const float*  __restrict__ coeff,
               const float*  __restrict__ bias,
               float4*       __restrict__ out)
{
    // Extended knot table over m = floor(index)+8 in [0,17]:
    //   bgn_w = m<=7 ? m+9 : m-8   (torch negative-index wrap folded in)
    //   end_w = m<=6 ? m+10 : m-7
    // entry = {v0, v1-v0, a0, a1-a0}  -> interp is a single FFMA each
    __shared__ float4 sT[18];
    if (threadIdx.x < 18) {
        int m  = threadIdx.x;
        int bw = (m <= 7) ? m + 9  : m - 8;
        int ew = (m <= 6) ? m + 10 : m - 7;
        float v0 = velocity[bw], v1 = velocity[ew];
        float a0 = angles[bw],   a1 = angles[ew];
        sT[m] = make_float4(v0, v1 - v0, a0, a1 - a0);
    }
    __syncthreads();

    const float cf = __ldg(coeff);
    const float bs = __ldg(bias);

    int idx = blockIdx.x * THREADS + threadIdx.x;
    if (idx >= TOTAL4) return;

    float4 d4 = __ldg(&data[idx]);
    float v[4] = {d4.x, d4.y, d4.z, d4.w};

    #pragma unroll
    for (int lane = 0; lane < 4; ++lane) {
        float d = v[lane];
        #pragma unroll
        for (int s = 0; s < NSTEPS; ++s) {
            float t  = f_tanh(fmaf(d, cf, bs));
            // w = index + 7.5 = 8.5 + 8.5*t  in [0, 17];  floor(index+8) = round(w)
            float w  = fmaf(t, 8.5f, 8.5f);
            float zb = w + MAGIC;                    // RN -> 12582912 + round(w)
            int   m  = __float_as_int(zb) & 0xFF;    // round(w) in [0,17]
            float fm = zb - MAGIC;                   // (float)m
            float pos = (w - fm) + 0.5f;             // z - floor(z)
            float4 tb = sT[m];                       // {v0, dv, a0, da}
            float velo = fmaf(pos, tb.y, tb.x);
            float ang  = fmaf(pos, tb.w, tb.z);
            float sn = f_sin(ang);
            float cs = f_cos(ang);
            float vs = velo * sn;
            float vc = velo * cs;
            float st = fmaf(d, vs, vc);              // velo*cos + d*velo*sin
            d = fmaf(st, 0.33333333333333333f, d);
        }
        v[lane] = d;
    }

    int c4 = idx & (IN_CH / 4 - 1);          // channel-quad within row
    int b  = idx >> 7;                       // batch row

    const float4* att4 = (const float4*)attention;
    float4 a0 = __ldg(&att4[2 * c4]);
    float4 a1 = __ldg(&att4[2 * c4 + 1]);

    float4 o0 = make_float4(a0.x * v[0], a0.y * v[0], a0.z * v[1], a0.w * v[1]);
    float4 o1 = make_float4(a1.x * v[2], a1.y * v[2], a1.z * v[3], a1.w * v[3]);

    int base = b * (OUT_CH / 4) + 2 * c4;
    out[base]     = o0;
    out[base + 1] = o1;
}

extern "C" void kernel_launch(void* const* d_in, const int* in_sizes, int n_in,
                              void* d_out, int out_size)
{
    const float4* data      = (const float4*)d_in[0];
    const float*  angles    = (const float*)d_in[1];
    const float*  velocity  = (const float*)d_in[2];
    const float*  attention = (const float*)d_in[3];
    const float*  coeff     = (const float*)d_in[4];
    const float*  bias      = (const float*)d_in[5];
    float4*       out       = (float4*)d_out;

    dim3 grid(TOTAL4 / THREADS);
    macunit_kernel<<<grid, THREADS>>>(data, angles, velocity, attention,
                                      coeff, bias, out);
}

// round 4
// speedup vs baseline: 1.2718x; 1.2718x over previous
#include <cuda_runtime.h>
#include <cuda_bf16.h>

#define BATCH       32768
#define IN_CH       512
#define OUT_CH      1024
#define NP          17
#define NSTEPS      3

#define TOTAL4      (BATCH * IN_CH / 4)     // 4,194,304 threads
#define THREADS     256

__device__ __forceinline__ float f_tanh(float x){ float r; asm("tanh.approx.f32 %0,%1;" : "=f"(r) : "f"(x)); return r; }
__device__ __forceinline__ float f_sin (float x){ float r; asm("sin.approx.f32 %0,%1;"  : "=f"(r) : "f"(x)); return r; }
__device__ __forceinline__ float f_cos (float x){ float r; asm("cos.approx.f32 %0,%1;"  : "=f"(r) : "f"(x)); return r; }

#define MAGIC 12582912.0f   // 2^23 + 2^22: w + MAGIC has round(w) in low mantissa bits

__global__ void __launch_bounds__(THREADS)
macunit_kernel(const float4* __restrict__ data,
               const float*  __restrict__ angles,
               const float*  __restrict__ velocity,
               const float*  __restrict__ attention,
               const float*  __restrict__ coeff,
               const float*  __restrict__ bias,
               float4*       __restrict__ out)
{
    // Extended knot table over m = floor(index)+8 in [0,17]:
    //   bgn_w = m<=7 ? m+9 : m-8   (torch negative-index wrap folded in)
    //   end_w = m<=6 ? m+10 : m-7
    // Entry layout: stride 5 floats -> bank(lane) = (5*m + c) % 32 is
    // collision-free across distinct m (5 odd, m < 18). Kills LDS conflicts.
    __shared__ float sT[18 * 5];
    if (threadIdx.x < 18) {
        int m  = threadIdx.x;
        int bw = (m <= 7) ? m + 9  : m - 8;
        int ew = (m <= 6) ? m + 10 : m - 7;
        float v0 = velocity[bw], v1 = velocity[ew];
        float a0 = angles[bw],   a1 = angles[ew];
        sT[m * 5 + 0] = v0;
        sT[m * 5 + 1] = v1 - v0;
        sT[m * 5 + 2] = a0;
        sT[m * 5 + 3] = a1 - a0;
        sT[m * 5 + 4] = 0.0f;
    }
    __syncthreads();

    const float cf = __ldg(coeff);
    const float bs = __ldg(bias);

    int idx = blockIdx.x * THREADS + threadIdx.x;   // grid covers TOTAL4 exactly

    float4 d4 = __ldg(&data[idx]);
    float v[4] = {d4.x, d4.y, d4.z, d4.w};

    #pragma unroll
    for (int lane = 0; lane < 4; ++lane) {
        float d = v[lane];
        #pragma unroll
        for (int s = 0; s < NSTEPS; ++s) {
            float t  = f_tanh(fmaf(d, cf, bs));
            // w = index + 7.5 = 8.5 + 8.5*t in [0,17]; floor(index+8) = round(w)
            float w  = fmaf(t, 8.5f, 8.5f);
            float zb = w + MAGIC;                    // RN -> 12582912 + round(w)
            int   m  = __float_as_int(zb) & 0xFF;    // round(w) in [0,17]
            float fm = zb - MAGIC;                   // (float)round(w)
            float pos = (w - fm) + 0.5f;             // frac(index+8)
            int off = m * 5;
            float v0 = sT[off + 0];
            float dv = sT[off + 1];
            float a0 = sT[off + 2];
            float da = sT[off + 3];
            float velo = fmaf(pos, dv, v0);
            float ang  = fmaf(pos, da, a0);
            float sn = f_sin(ang);
            float cs = f_cos(ang);
            float vs = velo * sn;
            float vc = velo * cs;
            float st = fmaf(d, vs, vc);              // velo*cos + d*velo*sin
            d = fmaf(st, 0.33333333333333333f, d);
        }
        v[lane] = d;
    }

    int c4 = idx & (IN_CH / 4 - 1);          // channel-quad within row
    int b  = idx >> 7;                       // batch row

    const float4* att4 = (const float4*)attention;
    float4 a0 = __ldg(&att4[2 * c4]);
    float4 a1 = __ldg(&att4[2 * c4 + 1]);

    float4 o0 = make_float4(a0.x * v[0], a0.y * v[0], a0.z * v[1], a0.w * v[1]);
    float4 o1 = make_float4(a1.x * v[2], a1.y * v[2], a1.z * v[3], a1.w * v[3]);

    int base = b * (OUT_CH / 4) + 2 * c4;
    out[base]     = o0;
    out[base + 1] = o1;
}

extern "C" void kernel_launch(void* const* d_in, const int* in_sizes, int n_in,
                              void* d_out, int out_size)
{
    const float4* data      = (const float4*)d_in[0];
    const float*  angles    = (const float*)d_in[1];
    const float*  velocity  = (const float*)d_in[2];
    const float*  attention = (const float*)d_in[3];
    const float*  coeff     = (const float*)d_in[4];
    const float*  bias      = (const float*)d_in[5];
    float4*       out       = (float4*)d_out;

    dim3 grid(TOTAL4 / THREADS);
    macunit_kernel<<<grid, THREADS>>>(data, angles, velocity, attention,
                                      coeff, bias, out);
}